// round 1
// baseline (speedup 1.0000x reference)
#include <cuda_runtime.h>
#include <math.h>

#define BSZ 512   // batch
#define CSZ 256   // concepts
#define NW  4     // uint64 words per concept row

// Scratch (device globals — no allocation allowed)
__device__ unsigned long long g_masks[BSZ * NW];
__device__ double g_acc[5];   // kl_img, kl_txt, kl_sim, bce_sum, mask_cnt

// ---------------------------------------------------------------------------
// Kernel 1: pack medical_concepts {-1,0,1} rows into 256-bit masks (1 if >0).
// One warp per row; lane reads concept (32*m + lane) -> ballot gives 32 bits.
// Block 0 also zeroes the accumulators.
// ---------------------------------------------------------------------------
__global__ void k_build_masks(const int* __restrict__ mc) {
    int gw   = (blockIdx.x * blockDim.x + threadIdx.x) >> 5;  // global warp = row
    int lane = threadIdx.x & 31;
    if (blockIdx.x == 0 && threadIdx.x < 5) g_acc[threadIdx.x] = 0.0;
    if (gw >= BSZ) return;

    unsigned m[8];
#pragma unroll
    for (int k = 0; k < 8; k++) {
        int v = mc[gw * CSZ + k * 32 + lane];
        m[k] = __ballot_sync(0xFFFFFFFFu, v > 0);
    }
    if (lane == 0) {
#pragma unroll
        for (int w = 0; w < 4; w++)
            g_masks[gw * NW + w] =
                (unsigned long long)m[2 * w] |
                ((unsigned long long)m[2 * w + 1] << 32);
    }
}

// ---------------------------------------------------------------------------
// Block-wide reduction over 256 threads (8 warps). Deterministic: all threads
// combine the 8 warp partials in the same fixed order.
// ---------------------------------------------------------------------------
template <bool IS_MAX>
__device__ __forceinline__ float bred(float v) {
    static __shared__ float red_s[8];
#pragma unroll
    for (int o = 16; o; o >>= 1) {
        float u = __shfl_xor_sync(0xFFFFFFFFu, v, o);
        v = IS_MAX ? fmaxf(v, u) : (v + u);
    }
    int w = threadIdx.x >> 5, l = threadIdx.x & 31;
    __syncthreads();                 // protect previous use of red_s
    if (l == 0) red_s[w] = v;
    __syncthreads();
    float r = red_s[0];
#pragma unroll
    for (int k = 1; k < 8; k++)
        r = IS_MAX ? fmaxf(r, red_s[k]) : (r + red_s[k]);
    return r;
}

// ---------------------------------------------------------------------------
// Kernel 2: one block per row i (512 blocks x 256 threads).
//  - builds sim row via popcounts on shared-staged masks
//  - softmax(sim*5) -> t_j  (shared by all three KL terms)
//  - row KL for each of the 3 logit matrices: sumtlogt - dot(t,x) + lse(x)
//  - masked BCE for this row's concept chunk
// ---------------------------------------------------------------------------
__global__ void k_rows(const float* __restrict__ limg,
                       const float* __restrict__ ltxt,
                       const float* __restrict__ clog,
                       const float* __restrict__ csim,
                       const int*   __restrict__ mc) {
    __shared__ unsigned long long smask[BSZ * NW];   // 16 KB
    const int tid = threadIdx.x;
    const int i   = blockIdx.x;

    for (int k = tid; k < BSZ * NW; k += 256) smask[k] = g_masks[k];
    __syncthreads();

    const unsigned long long a0 = smask[i * NW + 0];
    const unsigned long long a1 = smask[i * NW + 1];
    const unsigned long long a2 = smask[i * NW + 2];
    const unsigned long long a3 = smask[i * NW + 3];

    // --- sim row (each thread covers j = tid and j = tid+256) ---
    float s[2];
#pragma unroll
    for (int q = 0; q < 2; q++) {
        int j = tid + q * 256;
        const unsigned long long* b = &smask[j * NW];
        int inter = __popcll(a0 & b[0]) + __popcll(a1 & b[1]) +
                    __popcll(a2 & b[2]) + __popcll(a3 & b[3]);
        int uni   = __popcll(a0 | b[0]) + __popcll(a1 | b[1]) +
                    __popcll(a2 | b[2]) + __popcll(a3 | b[3]);
        float sim = (uni > 0) ? (float)inter / (float)uni : 0.0f;
        s[q] = sim * 5.0f;   // /TEMPERATURE (=0.2)
    }

    // --- softmax over sim row; also sum t*log t ---
    float m = bred<true>(fmaxf(s[0], s[1]));
    float e[2];
    float zp = 0.0f, wp = 0.0f;
#pragma unroll
    for (int q = 0; q < 2; q++) {
        e[q] = expf(s[q] - m);
        zp += e[q];
        wp += e[q] * (s[q] - m);
    }
    float Z = bred<false>(zp);
    float W = bred<false>(wp);
    float sumtlogt = W / Z - logf(Z);
    float invZ = 1.0f / Z;
    float t0 = e[0] * invZ, t1 = e[1] * invZ;

    // --- three KL terms against the same targets ---
    const float* mats[3];
    mats[0] = limg + (size_t)i * BSZ;
    mats[1] = ltxt + (size_t)i * BSZ;
    mats[2] = csim + (size_t)i * BSZ;
    float kl[3];
#pragma unroll
    for (int mi = 0; mi < 3; mi++) {
        const float* x = mats[mi];
        float x0 = x[tid], x1 = x[tid + 256];
        float mx  = bred<true>(fmaxf(x0, x1));
        float zep = expf(x0 - mx) + expf(x1 - mx);
        float dp  = t0 * x0 + t1 * x1;
        float Ze  = bred<false>(zep);
        float dot = bred<false>(dp);
        float lse = logf(Ze) + mx;
        kl[mi] = sumtlogt - dot + lse;
    }

    // --- masked BCE for row i of concepts (256 elements, 1/thread) ---
    int   v   = mc[i * CSZ + tid];
    float bce = 0.0f, cnt = 0.0f;
    if (v != -1) {
        float xv = clog[i * CSZ + tid];
        float tt = (float)v;
        bce = fmaxf(xv, 0.0f) - xv * tt + log1pf(expf(-fabsf(xv)));
        cnt = 1.0f;
    }
    float bsum = bred<false>(bce);
    float bcnt = bred<false>(cnt);

    if (tid == 0) {
        atomicAdd(&g_acc[0], (double)kl[0]);
        atomicAdd(&g_acc[1], (double)kl[1]);
        atomicAdd(&g_acc[2], (double)kl[2]);
        atomicAdd(&g_acc[3], (double)bsum);
        atomicAdd(&g_acc[4], (double)bcnt);
    }
}

// ---------------------------------------------------------------------------
// Kernel 3: finalize scalar.
// ---------------------------------------------------------------------------
__global__ void k_finalize(float* __restrict__ out) {
    double clip_loss        = (g_acc[0] + g_acc[1]) / (2.0 * BSZ);
    double concept_sim_loss = g_acc[2] / (double)BSZ;
    double concept_loss     = g_acc[3] / (g_acc[4] + 1e-8);
    out[0] = (float)(clip_loss + 0.2 * concept_loss + 0.2 * concept_sim_loss);
}

// ---------------------------------------------------------------------------
extern "C" void kernel_launch(void* const* d_in, const int* in_sizes, int n_in,
                              void* d_out, int out_size) {
    const float* limg = (const float*)d_in[0];  // logits_per_image  [512,512]
    const float* ltxt = (const float*)d_in[1];  // logits_per_text   [512,512]
    const float* clog = (const float*)d_in[2];  // concepts_logits   [512,256]
    const float* csim = (const float*)d_in[3];  // concepts_image_similarity [512,512]
    const int*   mc   = (const int*)  d_in[4];  // medical_concepts  [512,256]
    float* out = (float*)d_out;

    // 512 rows, one warp each: 32 blocks x 512 threads (16 warps)
    k_build_masks<<<32, 512>>>(mc);
    k_rows<<<BSZ, 256>>>(limg, ltxt, clog, csim, mc);
    k_finalize<<<1, 1>>>(out);
}

// round 2
// speedup vs baseline: 1.1234x; 1.1234x over previous
#include <cuda_runtime.h>
#include <math.h>

#define BSZ 512   // batch
#define CSZ 256   // concepts

// Scratch (device globals — no allocation allowed)
// Row-major 32-bit mask words: g_masks[r*8 + w] covers concepts [32w, 32w+32)
__device__ unsigned g_masks[BSZ * 8];
__device__ double   g_acc[4];     // kl01, kl2, bce_sum, mask_cnt
__device__ unsigned g_done;

// ---------------------------------------------------------------------------
// Kernel 1: word-per-thread mask build. 4096 threads, thread t builds word
// (r = t>>3, w = t&7) from 32 consecutive ints via 8 int4 loads. No cross-lane
// ops. Block 0 also zeroes the accumulators + completion counter.
// ---------------------------------------------------------------------------
__global__ void k_build(const int* __restrict__ mc) {
    if (blockIdx.x == 0) {
        if (threadIdx.x < 4) g_acc[threadIdx.x] = 0.0;
        else if (threadIdx.x == 4) g_done = 0u;
    }
    int t = blockIdx.x * blockDim.x + threadIdx.x;   // 0..4095
    int r = t >> 3, w = t & 7;
    const int4* p = (const int4*)(mc + r * CSZ + w * 32);
    unsigned bits = 0;
#pragma unroll
    for (int k = 0; k < 8; k++) {
        int4 v = p[k];
        bits |= (unsigned)(v.x > 0) << (4 * k + 0);
        bits |= (unsigned)(v.y > 0) << (4 * k + 1);
        bits |= (unsigned)(v.z > 0) << (4 * k + 2);
        bits |= (unsigned)(v.w > 0) << (4 * k + 3);
    }
    g_masks[r * 8 + w] = bits;
}

// ---------------------------------------------------------------------------
// Batched block reductions over 256 threads (8 warps). One __syncthreads each.
// Callers must pass disjoint buf regions across back-to-back calls.
// ---------------------------------------------------------------------------
template <int N>
__device__ __forceinline__ void red_max(float* v, float* buf) {
#pragma unroll
    for (int k = 0; k < N; k++)
#pragma unroll
        for (int o = 16; o; o >>= 1)
            v[k] = fmaxf(v[k], __shfl_xor_sync(0xFFFFFFFFu, v[k], o));
    int w = threadIdx.x >> 5, l = threadIdx.x & 31;
    if (l == 0)
#pragma unroll
        for (int k = 0; k < N; k++) buf[k * 8 + w] = v[k];
    __syncthreads();
#pragma unroll
    for (int k = 0; k < N; k++) {
        float r = buf[k * 8];
#pragma unroll
        for (int ww = 1; ww < 8; ww++) r = fmaxf(r, buf[k * 8 + ww]);
        v[k] = r;
    }
}

template <int N>
__device__ __forceinline__ void red_sum(float* v, float* buf) {
#pragma unroll
    for (int k = 0; k < N; k++)
#pragma unroll
        for (int o = 16; o; o >>= 1)
            v[k] += __shfl_xor_sync(0xFFFFFFFFu, v[k], o);
    int w = threadIdx.x >> 5, l = threadIdx.x & 31;
    if (l == 0)
#pragma unroll
        for (int k = 0; k < N; k++) buf[k * 8 + w] = v[k];
    __syncthreads();
#pragma unroll
    for (int k = 0; k < N; k++) {
        float r = buf[k * 8];
#pragma unroll
        for (int ww = 1; ww < 8; ww++) r += buf[k * 8 + ww];
        v[k] = r;
    }
}

// ---------------------------------------------------------------------------
// Kernel 2: one block per row i. Computes sim row (popcounts on smem masks),
// softmax targets, three KL row terms, masked BCE — 3 barrier phases total.
// Last block to finish computes the final scalar (fused finalize).
// ---------------------------------------------------------------------------
__global__ void __launch_bounds__(256) k_rows(
        const float* __restrict__ limg,
        const float* __restrict__ ltxt,
        const float* __restrict__ clog,
        const float* __restrict__ csim,
        const int*   __restrict__ mc,
        float* __restrict__ out) {
    __shared__ unsigned smask[BSZ * 8];   // 16 KB, row-major
    __shared__ float    rbuf[112];        // phase A: [0,32), phase B: [32,112)
    const int tid = threadIdx.x;
    const int i   = blockIdx.x;

    // Early global loads (overlap with mask staging)
    float x0[3], x1[3];
    x0[0] = limg[i * BSZ + tid]; x1[0] = limg[i * BSZ + tid + 256];
    x0[1] = ltxt[i * BSZ + tid]; x1[1] = ltxt[i * BSZ + tid + 256];
    x0[2] = csim[i * BSZ + tid]; x1[2] = csim[i * BSZ + tid + 256];
    int   mcv = mc[i * CSZ + tid];
    float xcv = clog[i * CSZ + tid];

    // Stage masks (1024 uint4 = 16 KB)
    {
        uint4* s4 = (uint4*)smask;
        const uint4* g4 = (const uint4*)g_masks;
        for (int k = tid; k < BSZ * 2; k += 256) s4[k] = g4[k];
    }
    __syncthreads();

    uint4 a_lo = *(const uint4*)&smask[i * 8];
    uint4 a_hi = *(const uint4*)&smask[i * 8 + 4];

    // sim row: thread covers j = tid and j = tid+256
    float s[2];
#pragma unroll
    for (int q = 0; q < 2; q++) {
        int j = q == 0 ? tid : tid + 256;
        uint4 b_lo = *(const uint4*)&smask[j * 8];
        uint4 b_hi = *(const uint4*)&smask[j * 8 + 4];
        int inter = __popc(a_lo.x & b_lo.x) + __popc(a_lo.y & b_lo.y) +
                    __popc(a_lo.z & b_lo.z) + __popc(a_lo.w & b_lo.w) +
                    __popc(a_hi.x & b_hi.x) + __popc(a_hi.y & b_hi.y) +
                    __popc(a_hi.z & b_hi.z) + __popc(a_hi.w & b_hi.w);
        int uni   = __popc(a_lo.x | b_lo.x) + __popc(a_lo.y | b_lo.y) +
                    __popc(a_lo.z | b_lo.z) + __popc(a_lo.w | b_lo.w) +
                    __popc(a_hi.x | b_hi.x) + __popc(a_hi.y | b_hi.y) +
                    __popc(a_hi.z | b_hi.z) + __popc(a_hi.w | b_hi.w);
        s[q] = (uni > 0) ? __fdividef(5.0f * (float)inter, (float)uni) : 0.0f;
    }

    // ---- Phase A: 4 maxes in one reduction ----
    float vA[4];
    vA[0] = fmaxf(s[0], s[1]);
    vA[1] = fmaxf(x0[0], x1[0]);
    vA[2] = fmaxf(x0[1], x1[1]);
    vA[3] = fmaxf(x0[2], x1[2]);
    red_max<4>(vA, rbuf);
    const float msim = vA[0];

    // ---- per-thread partials for phase B ----
    float d0 = s[0] - msim, d1 = s[1] - msim;
    float e0 = __expf(d0), e1 = __expf(d1);
    float vB[10];
    vB[0] = e0 + e1;                 // Z partial
    vB[1] = e0 * d0 + e1 * d1;       // W partial (sum e*(s-m))
#pragma unroll
    for (int m = 0; m < 3; m++) {
        vB[2 + 2 * m] = __expf(x0[m] - vA[1 + m]) + __expf(x1[m] - vA[1 + m]); // Ze
        vB[3 + 2 * m] = e0 * x0[m] + e1 * x1[m];                               // dot*Z
    }
    // masked BCE
    float bce = 0.0f, cnt = 0.0f;
    if (mcv != -1) {
        float tt = (float)mcv;
        bce = fmaxf(xcv, 0.0f) - xcv * tt + log1pf(__expf(-fabsf(xcv)));
        cnt = 1.0f;
    }
    vB[8] = bce;
    vB[9] = cnt;
    red_sum<10>(vB, rbuf + 32);

    if (tid == 0) {
        float Z = vB[0], W = vB[1];
        float invZ = __fdividef(1.0f, Z);
        float sumtlogt = W * invZ - __logf(Z);
        float kl0 = sumtlogt - vB[3] * invZ + __logf(vB[2]) + vA[1];
        float kl1 = sumtlogt - vB[5] * invZ + __logf(vB[4]) + vA[2];
        float kl2 = sumtlogt - vB[7] * invZ + __logf(vB[6]) + vA[3];
        atomicAdd(&g_acc[0], (double)(kl0 + kl1));
        atomicAdd(&g_acc[1], (double)kl2);
        atomicAdd(&g_acc[2], (double)vB[8]);
        atomicAdd(&g_acc[3], (double)vB[9]);
        __threadfence();
        unsigned old = atomicAdd(&g_done, 1u);
        if (old == BSZ - 1) {
            double a0 = atomicAdd(&g_acc[0], 0.0);
            double a1 = atomicAdd(&g_acc[1], 0.0);
            double a2 = atomicAdd(&g_acc[2], 0.0);
            double a3 = atomicAdd(&g_acc[3], 0.0);
            double clip_loss        = a0 / (2.0 * BSZ);
            double concept_sim_loss = a1 / (double)BSZ;
            double concept_loss     = a2 / (a3 + 1e-8);
            out[0] = (float)(clip_loss + 0.2 * concept_loss + 0.2 * concept_sim_loss);
        }
    }
}

// ---------------------------------------------------------------------------
extern "C" void kernel_launch(void* const* d_in, const int* in_sizes, int n_in,
                              void* d_out, int out_size) {
    const float* limg = (const float*)d_in[0];  // logits_per_image  [512,512]
    const float* ltxt = (const float*)d_in[1];  // logits_per_text   [512,512]
    const float* clog = (const float*)d_in[2];  // concepts_logits   [512,256]
    const float* csim = (const float*)d_in[3];  // concepts_image_similarity [512,512]
    const int*   mc   = (const int*)  d_in[4];  // medical_concepts  [512,256]
    float* out = (float*)d_out;

    k_build<<<32, 128>>>(mc);                           // 4096 threads
    k_rows<<<BSZ, 256>>>(limg, ltxt, clog, csim, mc, out);
}